// round 15
// baseline (speedup 1.0000x reference)
#include <cuda_runtime.h>

// out = x * (1 + softmax(leaky(semantic@W1^T + b1)@W2^T + b2))
// x: [B=8, C=256, H=256, W=256] fp32.
// SINGLE kernel: every block redundantly computes its batch's gate (weights
// are L2-hot), then streams its contiguous 1MB plane. No inter-block sync.

#define B 8
#define C 256
#define HW4 16384            // float4 per (b,c) plane
#define NBLK (B * C)         // 2048 blocks, one per plane
#define NT 256

__global__ __launch_bounds__(NT, 8)
void fused_kernel(const float4* __restrict__ x, float4* __restrict__ out,
                  const float* __restrict__ semantic,
                  const float* __restrict__ W1, const float* __restrict__ b1,
                  const float* __restrict__ W2, const float* __restrict__ b2)
{
    __shared__ float sem[C];
    __shared__ float hbuf[C];
    __shared__ float lbuf[C];
    __shared__ float red[8];

    const int plane = blockIdx.x;
    const int b     = plane >> 8;        // batch
    const int c     = plane & 255;       // this block's channel
    const int t     = threadIdx.x;       // 0..255
    const int lane  = t & 31;
    const int warp  = t >> 5;            // 0..7

    // ---- load semantic row (L2-hot after wave 1) ----
    sem[t] = semantic[b * C + t];
    __syncthreads();

    const float4* sem4 = (const float4*)sem;
    const float4 s0 = sem4[lane];
    const float4 s1 = sem4[lane + 32];

    // ---- stage 1: h = leaky(semantic @ W1^T + b1); 32 channels per warp ----
    #pragma unroll 2
    for (int i = 0; i < 32; i++) {
        const int ch = warp * 32 + i;
        const float4* w4 = (const float4*)(W1 + ch * C);
        const float4 a0 = w4[lane];
        const float4 a1 = w4[lane + 32];
        float d = a0.x*s0.x + a0.y*s0.y + a0.z*s0.z + a0.w*s0.w
                + a1.x*s1.x + a1.y*s1.y + a1.z*s1.z + a1.w*s1.w;
        #pragma unroll
        for (int o = 16; o > 0; o >>= 1) d += __shfl_xor_sync(0xFFFFFFFFu, d, o);
        if (lane == 0) {
            float h = d + b1[ch];
            hbuf[ch] = (h > 0.f) ? h : 0.1f * h;
        }
    }
    __syncthreads();

    const float4* h4 = (const float4*)hbuf;
    const float4 h0 = h4[lane];
    const float4 h1 = h4[lane + 32];

    // ---- stage 2: logits = h @ W2^T + b2 ----
    #pragma unroll 2
    for (int i = 0; i < 32; i++) {
        const int ch = warp * 32 + i;
        const float4* w4 = (const float4*)(W2 + ch * C);
        const float4 a0 = w4[lane];
        const float4 a1 = w4[lane + 32];
        float d = a0.x*h0.x + a0.y*h0.y + a0.z*h0.z + a0.w*h0.w
                + a1.x*h1.x + a1.y*h1.y + a1.z*h1.z + a1.w*h1.w;
        #pragma unroll
        for (int o = 16; o > 0; o >>= 1) d += __shfl_xor_sync(0xFFFFFFFFu, d, o);
        if (lane == 0) lbuf[ch] = d + b2[ch];
    }
    __syncthreads();

    // ---- softmax stats over 256 logits (one per thread) ----
    const float logit = lbuf[t];
    float m = logit;
    #pragma unroll
    for (int o = 16; o > 0; o >>= 1) m = fmaxf(m, __shfl_xor_sync(0xFFFFFFFFu, m, o));
    if (lane == 0) red[warp] = m;
    __syncthreads();
    if (t < 32) {
        float v = (lane < 8) ? red[lane] : -3.4e38f;
        #pragma unroll
        for (int o = 16; o > 0; o >>= 1) v = fmaxf(v, __shfl_xor_sync(0xFFFFFFFFu, v, o));
        if (lane == 0) red[0] = v;
    }
    __syncthreads();
    const float gmax = red[0];
    __syncthreads();

    float e = __expf(logit - gmax);
    float sum = e;
    #pragma unroll
    for (int o = 16; o > 0; o >>= 1) sum += __shfl_xor_sync(0xFFFFFFFFu, sum, o);
    if (lane == 0) red[warp] = sum;
    __syncthreads();
    if (t < 32) {
        float v = (lane < 8) ? red[lane] : 0.f;
        #pragma unroll
        for (int o = 16; o > 0; o >>= 1) v += __shfl_xor_sync(0xFFFFFFFFu, v, o);
        if (lane == 0) red[0] = v;
    }
    __syncthreads();
    const float gsum = red[0];

    // this block's gate scalar (identical in every thread)
    const float s = 1.f + __expf(lbuf[c] - gmax) / gsum;

    // ---- streaming phase: contiguous 1MB plane, proven 82%-DRAM structure ----
    const float4* xin = x + (size_t)plane * HW4;
    float4*       xo  = out + (size_t)plane * HW4;

    #pragma unroll 8
    for (int i = t; i < HW4; i += NT) {
        float4 v = xin[i];
        v.x *= s; v.y *= s; v.z *= s; v.w *= s;
        xo[i] = v;
    }
}

extern "C" void kernel_launch(void* const* d_in, const int* in_sizes, int n_in,
                              void* d_out, int out_size) {
    const float* x        = (const float*)d_in[0];
    const float* semantic = (const float*)d_in[1];
    const float* W1       = (const float*)d_in[2];
    const float* b1       = (const float*)d_in[3];
    const float* W2       = (const float*)d_in[4];
    const float* b2       = (const float*)d_in[5];
    float* out = (float*)d_out;

    fused_kernel<<<NBLK, NT>>>((const float4*)x, (float4*)out,
                               semantic, W1, b1, W2, b2);
}